// round 1
// baseline (speedup 1.0000x reference)
#include <cuda_runtime.h>
#include <cuda_bf16.h>

// Problem constants
#define B_   32
#define N_   4096
#define DK_  128
#define H_   128
#define A_   128
#define CH_  16              // chunks per batch row in score kernel
#define TILE_ (N_/CH_)       // 256 rows per score block

// ---------------- scratch (device globals; no allocation allowed) ----------
__device__ float g_zfea[B_*N_*A_];     // 67MB precomputed encoder features (+b_attn)
__device__ float g_P[B_*N_];           // unnormalized exp scores
__device__ float g_cov[B_*N_];         // coverage
__device__ float g_h[B_*H_];
__device__ float g_c[B_*H_];
__device__ float g_s[B_*DK_];          // previous context (LSTM input)
__device__ float g_dec[B_*A_];         // dec_fea for current step
__device__ float g_Sp[B_*CH_];         // partial softmax denominators
__device__ float g_CTp[B_*CH_*DK_];    // partial context vectors
__device__ float g_closs;
__device__ float g_WihT[DK_*4*H_];     // transposed LSTM weights [d][j]
__device__ float g_WhhT[H_*4*H_];

__device__ __forceinline__ float tanh_fast(float x) {
    float y;
    asm("tanh.approx.f32 %0, %1;" : "=f"(y) : "f"(x));
    return y;
}
__device__ __forceinline__ float sigmoid_f(float x) {
    return 1.0f / (1.0f + __expf(-x));
}

// ---------------- init: state reset (idempotent per launch) ----------------
__global__ void init_kernel(const float* __restrict__ h0, const float* __restrict__ c0) {
    int i = blockIdx.x * blockDim.x + threadIdx.x;
    int total = B_ * N_;
    for (int k = i; k < total; k += gridDim.x * blockDim.x) g_cov[k] = 0.0f;
    if (i < B_*H_) { g_h[i] = h0[i]; g_c[i] = c0[i]; }
    if (i < B_*DK_) g_s[i] = 0.0f;
    if (i == 0) g_closs = 0.0f;
}

// ---------------- transpose LSTM weights for coalesced reads ---------------
__global__ void transpose_kernel(const float* __restrict__ Wih, const float* __restrict__ Whh) {
    int i = blockIdx.x * blockDim.x + threadIdx.x;   // over 4H*DK = 65536
    if (i < 4*H_*DK_) {
        int j = i / DK_;      // gate row 0..511
        int d = i % DK_;      // input dim
        g_WihT[d*(4*H_) + j] = Wih[j*DK_ + d];
        g_WhhT[d*(4*H_) + j] = Whh[j*H_ + d];
    }
}

// ---------------- z_fea = z @ W_z + b_attn  (one-time GEMM) ----------------
// block: 256 threads, 64 rows x 128 cols output tile
__global__ void zfea_kernel(const float* __restrict__ z, const float* __restrict__ Wz,
                            const float* __restrict__ battn) {
    __shared__ float zs[64*DK_];    // 32KB
    int t = threadIdx.x;
    int rowBase = blockIdx.x * 64;
    // cooperative load of 64 z rows
    const float* zsrc = z + (size_t)rowBase * DK_;
    #pragma unroll
    for (int k = 0; k < 32; k++) zs[t + k*256] = zsrc[t + k*256];
    __syncthreads();

    int tx = t & 31;        // col group: cols tx*4..tx*4+3
    int ty = t >> 5;        // 0..7 -> rows ty + 8*i
    float acc[8][4];
    #pragma unroll
    for (int i = 0; i < 8; i++)
        #pragma unroll
        for (int c = 0; c < 4; c++) acc[i][c] = 0.0f;

    const float4* Wz4 = (const float4*)Wz;
    #pragma unroll 4
    for (int d = 0; d < DK_; d++) {
        float4 w = __ldg(&Wz4[d*32 + tx]);
        #pragma unroll
        for (int i = 0; i < 8; i++) {
            float zv = zs[(ty + 8*i)*DK_ + d];
            acc[i][0] = fmaf(zv, w.x, acc[i][0]);
            acc[i][1] = fmaf(zv, w.y, acc[i][1]);
            acc[i][2] = fmaf(zv, w.z, acc[i][2]);
            acc[i][3] = fmaf(zv, w.w, acc[i][3]);
        }
    }
    float4 bb = __ldg(&((const float4*)battn)[tx]);
    float4* outp = (float4*)g_zfea;
    #pragma unroll
    for (int i = 0; i < 8; i++) {
        int r = rowBase + ty + 8*i;
        float4 v4;
        v4.x = acc[i][0] + bb.x; v4.y = acc[i][1] + bb.y;
        v4.z = acc[i][2] + bb.z; v4.w = acc[i][3] + bb.w;
        outp[(size_t)r*32 + tx] = v4;
    }
}

// ---------------- LSTM cell + dec_fea (one block per batch elem) -----------
__global__ void lstm_kernel(const float* __restrict__ bih, const float* __restrict__ bhh,
                            const float* __restrict__ Wx) {
    int b = blockIdx.x;
    int j = threadIdx.x;            // 0..511
    __shared__ float s_s[DK_], h_s[H_], gates[4*H_], xs[2*H_];
    if (j < DK_) s_s[j] = g_s[b*DK_ + j];
    if (j < H_)  h_s[j] = g_h[b*H_ + j];
    __syncthreads();

    float acc = bih[j] + bhh[j];
    #pragma unroll 4
    for (int d = 0; d < DK_; d++) acc = fmaf(s_s[d], g_WihT[d*(4*H_) + j], acc);
    #pragma unroll 4
    for (int d = 0; d < H_; d++)  acc = fmaf(h_s[d], g_WhhT[d*(4*H_) + j], acc);
    gates[j] = acc;
    __syncthreads();

    if (j < H_) {
        float ig = sigmoid_f(gates[j]);
        float fg = sigmoid_f(gates[H_ + j]);
        float gg = tanhf(gates[2*H_ + j]);
        float og = sigmoid_f(gates[3*H_ + j]);
        float cold = g_c[b*H_ + j];
        float cn = fg * cold + ig * gg;
        float hn = og * tanhf(cn);
        g_c[b*H_ + j] = cn;
        g_h[b*H_ + j] = hn;
        xs[j] = hn;
        xs[H_ + j] = cn;
    }
    __syncthreads();

    if (j < A_) {
        float d = 0.0f;
        #pragma unroll 4
        for (int k = 0; k < 2*H_; k++) d = fmaf(xs[k], Wx[k*A_ + j], d);
        g_dec[b*A_ + j] = d;
    }
}

// ---------------- attention scores + partial context (the hot kernel) ------
// grid (CH_, B_), block 256 (8 warps); warp processes TILE_/8 = 32 rows
__global__ __launch_bounds__(256) void score_kernel(
        const float* __restrict__ z, const float* __restrict__ mask,
        const float* __restrict__ wc, const float* __restrict__ v) {
    int b = blockIdx.y, chunk = blockIdx.x;
    int warp = threadIdx.x >> 5, lane = threadIdx.x & 31;

    float4 dec4 = *(const float4*)&g_dec[b*A_ + lane*4];
    float4 wc4  = __ldg(&((const float4*)wc)[lane]);
    float4 v4   = __ldg(&((const float4*)v)[lane]);

    float4 ct = make_float4(0.f, 0.f, 0.f, 0.f);
    float Sacc = 0.0f;

    int n0 = chunk * TILE_ + warp * (TILE_/8);
    const float4* zf4p = (const float4*)g_zfea;
    const float4* z4p  = (const float4*)z;

    #pragma unroll 2
    for (int r = 0; r < TILE_/8; r++) {
        int idx = b*N_ + n0 + r;
        float cov = g_cov[idx];
        float m   = __ldg(&mask[idx]);
        float4 zf = zf4p[(size_t)idx*32 + lane];
        float t0 = tanh_fast(fmaf(cov, wc4.x, zf.x) + dec4.x);
        float t1 = tanh_fast(fmaf(cov, wc4.y, zf.y) + dec4.y);
        float t2 = tanh_fast(fmaf(cov, wc4.z, zf.z) + dec4.z);
        float t3 = tanh_fast(fmaf(cov, wc4.w, zf.w) + dec4.w);
        float e = v4.x*t0 + v4.y*t1 + v4.z*t2 + v4.w*t3;
        #pragma unroll
        for (int o = 16; o > 0; o >>= 1) e += __shfl_xor_sync(0xffffffffu, e, o);
        // e bounded by ||v||_1 (~9): exp(e) cannot overflow, skip global max
        float p = (m > 0.0f) ? __expf(e) : 0.0f;
        float4 zr = __ldg(&z4p[(size_t)idx*32 + lane]);
        ct.x = fmaf(p, zr.x, ct.x);
        ct.y = fmaf(p, zr.y, ct.y);
        ct.z = fmaf(p, zr.z, ct.z);
        ct.w = fmaf(p, zr.w, ct.w);
        if (lane == 0) { g_P[idx] = p; Sacc += p; }
    }

    __shared__ float sct[DK_];
    __shared__ float sS[8];
    if (threadIdx.x < DK_) sct[threadIdx.x] = 0.0f;
    if (lane == 0) sS[warp] = Sacc;
    __syncthreads();
    atomicAdd(&sct[lane*4 + 0], ct.x);
    atomicAdd(&sct[lane*4 + 1], ct.y);
    atomicAdd(&sct[lane*4 + 2], ct.z);
    atomicAdd(&sct[lane*4 + 3], ct.w);
    __syncthreads();
    if (threadIdx.x < DK_)
        g_CTp[(b*CH_ + chunk)*DK_ + threadIdx.x] = sct[threadIdx.x];
    if (threadIdx.x == 0) {
        float S = 0.0f;
        #pragma unroll
        for (int w = 0; w < 8; w++) S += sS[w];
        g_Sp[b*CH_ + chunk] = S;
    }
}

// ---------------- finalize: normalize, outputs, coverage, closs, s=ct ------
// grid (N_/1024, B_), block 256; thread handles 4 consecutive n
__global__ __launch_bounds__(256) void finalize_kernel(float* __restrict__ out, int t, int T) {
    int b = blockIdx.y;
    float S = 0.0f;
    #pragma unroll
    for (int ch = 0; ch < CH_; ch++) S += g_Sp[b*CH_ + ch];
    float invS = 1.0f / S;

    // chunk 0 blocks also produce ct -> text output + next LSTM input
    if (blockIdx.x == 0 && threadIdx.x < DK_) {
        float ctv = 0.0f;
        #pragma unroll
        for (int ch = 0; ch < CH_; ch++) ctv += g_CTp[(b*CH_ + ch)*DK_ + threadIdx.x];
        ctv *= invS;
        out[(size_t)(b*T + t)*DK_ + threadIdx.x] = ctv;
        g_s[b*DK_ + threadIdx.x] = ctv;
    }

    size_t OUT_ATT = (size_t)B_ * T * DK_;
    int nbase = blockIdx.x*1024 + threadIdx.x*4;
    int idx = b*N_ + nbase;
    float4 p4 = *(const float4*)&g_P[idx];
    float4 cov4 = *(const float4*)&g_cov[idx];
    float4 attn4;
    attn4.x = p4.x * invS; attn4.y = p4.y * invS;
    attn4.z = p4.z * invS; attn4.w = p4.w * invS;
    // coverage loss uses coverage BEFORE update
    float cl = fminf(attn4.x, cov4.x) + fminf(attn4.y, cov4.y)
             + fminf(attn4.z, cov4.z) + fminf(attn4.w, cov4.w);
    float4 ncov;
    ncov.x = cov4.x + attn4.x; ncov.y = cov4.y + attn4.y;
    ncov.z = cov4.z + attn4.z; ncov.w = cov4.w + attn4.w;
    *(float4*)&g_cov[idx] = ncov;
    *(float4*)&out[OUT_ATT + (size_t)(b*T + t)*N_ + nbase] = attn4;

    #pragma unroll
    for (int o = 16; o > 0; o >>= 1) cl += __shfl_xor_sync(0xffffffffu, cl, o);
    __shared__ float swr[8];
    int warp = threadIdx.x >> 5, lane = threadIdx.x & 31;
    if (lane == 0) swr[warp] = cl;
    __syncthreads();
    if (threadIdx.x == 0) {
        float s = 0.0f;
        #pragma unroll
        for (int w = 0; w < 8; w++) s += swr[w];
        atomicAdd(&g_closs, s / (float)B_);
    }
}

__global__ void closs_write_kernel(float* __restrict__ out, int out_size) {
    out[out_size - 1] = g_closs;
}

// ---------------- host driver ----------------------------------------------
extern "C" void kernel_launch(void* const* d_in, const int* in_sizes, int n_in,
                              void* d_out, int out_size) {
    const float* z     = (const float*)d_in[0];
    const float* mask  = (const float*)d_in[1];
    const float* h0    = (const float*)d_in[2];
    const float* c0    = (const float*)d_in[3];
    const float* W_ih  = (const float*)d_in[4];
    const float* W_hh  = (const float*)d_in[5];
    const float* b_ih  = (const float*)d_in[6];
    const float* b_hh  = (const float*)d_in[7];
    const float* W_x   = (const float*)d_in[8];
    const float* W_z   = (const float*)d_in[9];
    const float* w_c   = (const float*)d_in[10];
    const float* b_attn= (const float*)d_in[11];
    const float* v     = (const float*)d_in[12];
    float* out = (float*)d_out;

    // derive step count from output buffer size: out = B*T*DK + B*T*N + 1
    int T = (out_size - 1) / (B_ * (DK_ + N_));

    init_kernel<<<(B_*N_ + 255)/256, 256>>>(h0, c0);
    transpose_kernel<<<(4*H_*DK_ + 255)/256, 256>>>(W_ih, W_hh);
    zfea_kernel<<<(B_*N_)/64, 256>>>(z, W_z, b_attn);

    for (int t = 0; t < T; t++) {
        lstm_kernel<<<B_, 512>>>(b_ih, b_hh, W_x);
        score_kernel<<<dim3(CH_, B_), 256>>>(z, mask, w_c, v);
        finalize_kernel<<<dim3(N_/1024, B_), 256>>>(out, t, T);
    }
    closs_write_kernel<<<1, 1>>>(out, out_size);
}

// round 2
// speedup vs baseline: 1.4199x; 1.4199x over previous
#include <cuda_runtime.h>
#include <cuda_bf16.h>

// Problem constants
#define B_   32
#define N_   4096
#define DK_  128
#define H_   128
#define A_   128
#define CH_  16              // chunks per batch row in score kernel
#define TILE_ (N_/CH_)       // 256 rows per score block

// ---------------- scratch (device globals; no allocation allowed) ----------
__device__ float g_zfea[B_*N_*A_];     // 67MB precomputed encoder features (+b_attn)
__device__ float g_P[B_*N_];           // unnormalized exp scores
__device__ float g_cov[B_*N_];         // coverage
__device__ float g_h[B_*H_];
__device__ float g_c[B_*H_];
__device__ float g_s[B_*DK_];          // previous context (LSTM input)
__device__ float g_dec[B_*A_];         // dec_fea for current step
__device__ float g_Sp[B_*CH_];         // partial softmax denominators
__device__ float g_CTp[B_*CH_*DK_];    // partial context vectors
__device__ float g_closs;
__device__ float g_WxT[A_*2*H_];       // transposed W_x: [A][2H]

__device__ __forceinline__ float tanh_fast(float x) {
    float y;
    asm("tanh.approx.f32 %0, %1;" : "=f"(y) : "f"(x));
    return y;
}
__device__ __forceinline__ float sigmoid_f(float x) {
    return 1.0f / (1.0f + __expf(-x));
}

// ---------------- init: state reset (idempotent per launch) ----------------
__global__ void init_kernel(const float* __restrict__ h0, const float* __restrict__ c0) {
    int i = blockIdx.x * blockDim.x + threadIdx.x;
    int total = B_ * N_;
    for (int k = i; k < total; k += gridDim.x * blockDim.x) g_cov[k] = 0.0f;
    if (i < B_*H_) { g_h[i] = h0[i]; g_c[i] = c0[i]; }
    if (i < B_*DK_) g_s[i] = 0.0f;
    if (i == 0) g_closs = 0.0f;
}

// ---------------- transpose W_x for coalesced warp-split dots --------------
__global__ void transpose_kernel(const float* __restrict__ Wx) {
    int i = blockIdx.x * blockDim.x + threadIdx.x;   // over 2H*A = 32768
    if (i < 2*H_*A_) {
        int k = i / A_;       // input dim 0..255
        int j = i % A_;       // output dim 0..127
        g_WxT[j*(2*H_) + k] = Wx[k*A_ + j];
    }
}

// ---------------- z_fea = z @ W_z + b_attn  (one-time GEMM) ----------------
// block: 256 threads, 64 rows x 128 cols output tile
__global__ void zfea_kernel(const float* __restrict__ z, const float* __restrict__ Wz,
                            const float* __restrict__ battn) {
    __shared__ float zs[64*DK_];    // 32KB
    int t = threadIdx.x;
    int rowBase = blockIdx.x * 64;
    const float* zsrc = z + (size_t)rowBase * DK_;
    #pragma unroll
    for (int k = 0; k < 32; k++) zs[t + k*256] = zsrc[t + k*256];
    __syncthreads();

    int tx = t & 31;        // col group: cols tx*4..tx*4+3
    int ty = t >> 5;        // 0..7 -> rows ty + 8*i
    float acc[8][4];
    #pragma unroll
    for (int i = 0; i < 8; i++)
        #pragma unroll
        for (int c = 0; c < 4; c++) acc[i][c] = 0.0f;

    const float4* Wz4 = (const float4*)Wz;
    #pragma unroll 4
    for (int d = 0; d < DK_; d++) {
        float4 w = __ldg(&Wz4[d*32 + tx]);
        #pragma unroll
        for (int i = 0; i < 8; i++) {
            float zv = zs[(ty + 8*i)*DK_ + d];
            acc[i][0] = fmaf(zv, w.x, acc[i][0]);
            acc[i][1] = fmaf(zv, w.y, acc[i][1]);
            acc[i][2] = fmaf(zv, w.z, acc[i][2]);
            acc[i][3] = fmaf(zv, w.w, acc[i][3]);
        }
    }
    float4 bb = __ldg(&((const float4*)battn)[tx]);
    float4* outp = (float4*)g_zfea;
    #pragma unroll
    for (int i = 0; i < 8; i++) {
        int r = rowBase + ty + 8*i;
        float4 v4;
        v4.x = acc[i][0] + bb.x; v4.y = acc[i][1] + bb.y;
        v4.z = acc[i][2] + bb.z; v4.w = acc[i][3] + bb.w;
        outp[(size_t)r*32 + tx] = v4;
    }
}

// ---------------- LSTM cell + dec_fea: warp-split dot products -------------
// grid 32 (one block per batch elem), block 512 = 16 warps.
// Gates: 512 outputs, warp w computes j = w*32..w*32+31; lane covers 4 dims of
// s-part and 4 dims of h-part per output via float4 loads of the row-major
// weight matrices (coalesced across lanes), butterfly-reduced.
__global__ __launch_bounds__(512) void lstm_kernel(
        const float* __restrict__ Wih, const float* __restrict__ Whh,
        const float* __restrict__ bih, const float* __restrict__ bhh) {
    int b = blockIdx.x;
    int warp = threadIdx.x >> 5, lane = threadIdx.x & 31;
    __shared__ float x_in[2*H_];   // s(128) | h(128)
    __shared__ float gates[4*H_];
    __shared__ float xs[2*H_];     // h_new | c_new

    if (threadIdx.x < H_)           x_in[threadIdx.x] = g_s[b*DK_ + threadIdx.x];
    else if (threadIdx.x < 2*H_)    x_in[threadIdx.x] = g_h[b*H_ + (threadIdx.x - H_)];
    __syncthreads();

    float4 xa = *(const float4*)&x_in[lane*4];         // s dims 4l..4l+3
    float4 xb = *(const float4*)&x_in[H_ + lane*4];    // h dims 4l..4l+3
    const float4* Wih4 = (const float4*)Wih;
    const float4* Whh4 = (const float4*)Whh;

    #pragma unroll 4
    for (int k = 0; k < 32; k++) {
        int j = warp*32 + k;
        float4 wa = __ldg(&Wih4[j*32 + lane]);
        float4 wb = __ldg(&Whh4[j*32 + lane]);
        float acc = wa.x*xa.x + wa.y*xa.y + wa.z*xa.z + wa.w*xa.w
                  + wb.x*xb.x + wb.y*xb.y + wb.z*xb.z + wb.w*xb.w;
        #pragma unroll
        for (int o = 16; o > 0; o >>= 1) acc += __shfl_xor_sync(0xffffffffu, acc, o);
        if (lane == 0) gates[j] = acc + __ldg(&bih[j]) + __ldg(&bhh[j]);
    }
    __syncthreads();

    if (threadIdx.x < H_) {
        int j = threadIdx.x;
        float ig = sigmoid_f(gates[j]);
        float fg = sigmoid_f(gates[H_ + j]);
        float gg = tanhf(gates[2*H_ + j]);
        float og = sigmoid_f(gates[3*H_ + j]);
        float cold = g_c[b*H_ + j];
        float cn = fg * cold + ig * gg;
        float hn = og * tanhf(cn);
        g_c[b*H_ + j] = cn;
        g_h[b*H_ + j] = hn;
        xs[j] = hn;
        xs[H_ + j] = cn;
    }
    __syncthreads();

    // dec_fea: 128 outputs, warp w computes j = w*8..w*8+7; lane covers 8 of
    // 256 input dims (two float4 loads from transposed W_x rows).
    float4 ya = *(const float4*)&xs[lane*8];
    float4 yb = *(const float4*)&xs[lane*8 + 4];
    const float4* WxT4 = (const float4*)g_WxT;
    #pragma unroll
    for (int k = 0; k < 8; k++) {
        int j = warp*8 + k;
        float4 wa = WxT4[j*64 + lane*2];
        float4 wb = WxT4[j*64 + lane*2 + 1];
        float acc = wa.x*ya.x + wa.y*ya.y + wa.z*ya.z + wa.w*ya.w
                  + wb.x*yb.x + wb.y*yb.y + wb.z*yb.z + wb.w*yb.w;
        #pragma unroll
        for (int o = 16; o > 0; o >>= 1) acc += __shfl_xor_sync(0xffffffffu, acc, o);
        if (lane == 0) g_dec[b*A_ + j] = acc;
    }
}

// ---------------- attention scores + partial context (the hot kernel) ------
// grid (CH_, B_), block 256 (8 warps); warp processes TILE_/8 = 32 rows
__global__ __launch_bounds__(256) void score_kernel(
        const float* __restrict__ z, const float* __restrict__ mask,
        const float* __restrict__ wc, const float* __restrict__ v) {
    int b = blockIdx.y, chunk = blockIdx.x;
    int warp = threadIdx.x >> 5, lane = threadIdx.x & 31;

    float4 dec4 = *(const float4*)&g_dec[b*A_ + lane*4];
    float4 wc4  = __ldg(&((const float4*)wc)[lane]);
    float4 v4   = __ldg(&((const float4*)v)[lane]);

    float4 ct = make_float4(0.f, 0.f, 0.f, 0.f);
    float Sacc = 0.0f;

    int n0 = chunk * TILE_ + warp * (TILE_/8);
    const float4* zf4p = (const float4*)g_zfea;
    const float4* z4p  = (const float4*)z;

    #pragma unroll 2
    for (int r = 0; r < TILE_/8; r++) {
        int idx = b*N_ + n0 + r;
        float cov = g_cov[idx];
        float m   = __ldg(&mask[idx]);
        float4 zf = zf4p[(size_t)idx*32 + lane];
        float t0 = tanh_fast(fmaf(cov, wc4.x, zf.x) + dec4.x);
        float t1 = tanh_fast(fmaf(cov, wc4.y, zf.y) + dec4.y);
        float t2 = tanh_fast(fmaf(cov, wc4.z, zf.z) + dec4.z);
        float t3 = tanh_fast(fmaf(cov, wc4.w, zf.w) + dec4.w);
        float e = v4.x*t0 + v4.y*t1 + v4.z*t2 + v4.w*t3;
        #pragma unroll
        for (int o = 16; o > 0; o >>= 1) e += __shfl_xor_sync(0xffffffffu, e, o);
        // e bounded by ||v||_1 (~9): exp(e) cannot overflow, skip global max
        float p = (m > 0.0f) ? __expf(e) : 0.0f;
        float4 zr = __ldg(&z4p[(size_t)idx*32 + lane]);
        ct.x = fmaf(p, zr.x, ct.x);
        ct.y = fmaf(p, zr.y, ct.y);
        ct.z = fmaf(p, zr.z, ct.z);
        ct.w = fmaf(p, zr.w, ct.w);
        if (lane == 0) { g_P[idx] = p; Sacc += p; }
    }

    __shared__ float sct[DK_];
    __shared__ float sS[8];
    if (threadIdx.x < DK_) sct[threadIdx.x] = 0.0f;
    if (lane == 0) sS[warp] = Sacc;
    __syncthreads();
    atomicAdd(&sct[lane*4 + 0], ct.x);
    atomicAdd(&sct[lane*4 + 1], ct.y);
    atomicAdd(&sct[lane*4 + 2], ct.z);
    atomicAdd(&sct[lane*4 + 3], ct.w);
    __syncthreads();
    if (threadIdx.x < DK_)
        g_CTp[(b*CH_ + chunk)*DK_ + threadIdx.x] = sct[threadIdx.x];
    if (threadIdx.x == 0) {
        float S = 0.0f;
        #pragma unroll
        for (int w = 0; w < 8; w++) S += sS[w];
        g_Sp[b*CH_ + chunk] = S;
    }
}

// ---------------- finalize: normalize, outputs, coverage, closs, s=ct ------
// grid (N_/1024, B_), block 256; thread handles 4 consecutive n
__global__ __launch_bounds__(256) void finalize_kernel(float* __restrict__ out, int t, int T) {
    int b = blockIdx.y;
    float S = 0.0f;
    #pragma unroll
    for (int ch = 0; ch < CH_; ch++) S += g_Sp[b*CH_ + ch];
    float invS = 1.0f / S;

    // chunk 0 blocks also produce ct -> text output + next LSTM input
    if (blockIdx.x == 0 && threadIdx.x < DK_) {
        float ctv = 0.0f;
        #pragma unroll
        for (int ch = 0; ch < CH_; ch++) ctv += g_CTp[(b*CH_ + ch)*DK_ + threadIdx.x];
        ctv *= invS;
        out[(size_t)(b*T + t)*DK_ + threadIdx.x] = ctv;
        g_s[b*DK_ + threadIdx.x] = ctv;
    }

    size_t OUT_ATT = (size_t)B_ * T * DK_;
    int nbase = blockIdx.x*1024 + threadIdx.x*4;
    int idx = b*N_ + nbase;
    float4 p4 = *(const float4*)&g_P[idx];
    float4 cov4 = *(const float4*)&g_cov[idx];
    float4 attn4;
    attn4.x = p4.x * invS; attn4.y = p4.y * invS;
    attn4.z = p4.z * invS; attn4.w = p4.w * invS;
    // coverage loss uses coverage BEFORE update
    float cl = fminf(attn4.x, cov4.x) + fminf(attn4.y, cov4.y)
             + fminf(attn4.z, cov4.z) + fminf(attn4.w, cov4.w);
    float4 ncov;
    ncov.x = cov4.x + attn4.x; ncov.y = cov4.y + attn4.y;
    ncov.z = cov4.z + attn4.z; ncov.w = cov4.w + attn4.w;
    *(float4*)&g_cov[idx] = ncov;
    *(float4*)&out[OUT_ATT + (size_t)(b*T + t)*N_ + nbase] = attn4;

    #pragma unroll
    for (int o = 16; o > 0; o >>= 1) cl += __shfl_xor_sync(0xffffffffu, cl, o);
    __shared__ float swr[8];
    int warp = threadIdx.x >> 5, lane = threadIdx.x & 31;
    if (lane == 0) swr[warp] = cl;
    __syncthreads();
    if (threadIdx.x == 0) {
        float s = 0.0f;
        #pragma unroll
        for (int w = 0; w < 8; w++) s += swr[w];
        atomicAdd(&g_closs, s / (float)B_);
    }
}

__global__ void closs_write_kernel(float* __restrict__ out, int out_size) {
    out[out_size - 1] = g_closs;
}

// ---------------- host driver ----------------------------------------------
extern "C" void kernel_launch(void* const* d_in, const int* in_sizes, int n_in,
                              void* d_out, int out_size) {
    const float* z     = (const float*)d_in[0];
    const float* mask  = (const float*)d_in[1];
    const float* h0    = (const float*)d_in[2];
    const float* c0    = (const float*)d_in[3];
    const float* W_ih  = (const float*)d_in[4];
    const float* W_hh  = (const float*)d_in[5];
    const float* b_ih  = (const float*)d_in[6];
    const float* b_hh  = (const float*)d_in[7];
    const float* W_x   = (const float*)d_in[8];
    const float* W_z   = (const float*)d_in[9];
    const float* w_c   = (const float*)d_in[10];
    const float* b_attn= (const float*)d_in[11];
    const float* v     = (const float*)d_in[12];
    float* out = (float*)d_out;

    // derive step count from output buffer size: out = B*T*DK + B*T*N + 1
    int T = (out_size - 1) / (B_ * (DK_ + N_));

    init_kernel<<<(B_*N_ + 255)/256, 256>>>(h0, c0);
    transpose_kernel<<<(2*H_*A_ + 255)/256, 256>>>(W_x);
    zfea_kernel<<<(B_*N_)/64, 256>>>(z, W_z, b_attn);

    for (int t = 0; t < T; t++) {
        lstm_kernel<<<B_, 512>>>(W_ih, W_hh, b_ih, b_hh);
        score_kernel<<<dim3(CH_, B_), 256>>>(z, mask, w_c, v);
        finalize_kernel<<<dim3(N_/1024, B_), 256>>>(out, t, T);
    }
    closs_write_kernel<<<1, 1>>>(out, out_size);
}

// round 3
// speedup vs baseline: 1.4250x; 1.0036x over previous
#include <cuda_runtime.h>
#include <cuda_fp16.h>
#include <cuda_bf16.h>

// Problem constants
#define B_   32
#define N_   4096
#define DK_  128
#define H_   128
#define A_   128
#define CH_  16              // chunks per batch row in score kernel
#define TILE_ (N_/CH_)       // 256 rows per score block

// ---------------- scratch (device globals; no allocation allowed) ----------
__device__ __half g_zfh[B_*N_*A_];     // 33.5MB precomputed encoder features (+b_attn), fp16
__device__ float g_P[B_*N_];           // unnormalized exp scores
__device__ float g_cov[B_*N_];         // coverage
__device__ float g_xT[2][256*B_];      // k-major x = [s|h], double buffered: [k][b]
__device__ float g_cT[H_*B_];          // k-major cell state [j][b]
__device__ float g_xnT[256*B_];        // k-major [h_new|c_new] for dec_fea
__device__ float g_dec[B_*A_];         // dec_fea for current step
__device__ float g_Sp[B_*CH_];         // partial softmax denominators
__device__ float g_CTp[B_*CH_*DK_];    // partial context vectors
__device__ float g_closs;

__device__ __forceinline__ float tanh_fast(float x) {
    float y;
    asm("tanh.approx.f32 %0, %1;" : "=f"(y) : "f"(x));
    return y;
}
__device__ __forceinline__ float sigmoid_f(float x) {
    return 1.0f / (1.0f + __expf(-x));
}

// ---------------- init: state reset (idempotent per launch) ----------------
__global__ void init_kernel(const float* __restrict__ h0, const float* __restrict__ c0) {
    int i = blockIdx.x * blockDim.x + threadIdx.x;
    int total = B_ * N_;
    for (int k = i; k < total; k += gridDim.x * blockDim.x) g_cov[k] = 0.0f;
    if (i < B_*H_) {
        int b = i >> 7, j = i & 127;
        g_xT[0][j*B_ + b] = 0.0f;              // s = 0
        g_xT[0][(H_+j)*B_ + b] = h0[i];        // h = h0
        g_cT[j*B_ + b] = c0[i];
    }
    if (i == 0) g_closs = 0.0f;
}

// ---------------- z_fea = z @ W_z + b_attn  (one-time GEMM, fp16 out) ------
// block: 256 threads, 64 rows x 128 cols output tile
__global__ void zfea_kernel(const float* __restrict__ z, const float* __restrict__ Wz,
                            const float* __restrict__ battn) {
    __shared__ float zs[64*DK_];    // 32KB
    int t = threadIdx.x;
    int rowBase = blockIdx.x * 64;
    const float* zsrc = z + (size_t)rowBase * DK_;
    #pragma unroll
    for (int k = 0; k < 32; k++) zs[t + k*256] = zsrc[t + k*256];
    __syncthreads();

    int tx = t & 31;        // col group: cols tx*4..tx*4+3
    int ty = t >> 5;        // 0..7 -> rows ty + 8*i
    float acc[8][4];
    #pragma unroll
    for (int i = 0; i < 8; i++)
        #pragma unroll
        for (int c = 0; c < 4; c++) acc[i][c] = 0.0f;

    const float4* Wz4 = (const float4*)Wz;
    #pragma unroll 4
    for (int d = 0; d < DK_; d++) {
        float4 w = __ldg(&Wz4[d*32 + tx]);
        #pragma unroll
        for (int i = 0; i < 8; i++) {
            float zv = zs[(ty + 8*i)*DK_ + d];
            acc[i][0] = fmaf(zv, w.x, acc[i][0]);
            acc[i][1] = fmaf(zv, w.y, acc[i][1]);
            acc[i][2] = fmaf(zv, w.z, acc[i][2]);
            acc[i][3] = fmaf(zv, w.w, acc[i][3]);
        }
    }
    float4 bb = __ldg(&((const float4*)battn)[tx]);
    __half2* outp = (__half2*)g_zfh;
    #pragma unroll
    for (int i = 0; i < 8; i++) {
        size_t r = rowBase + ty + 8*i;
        outp[r*64 + tx*2]     = __floats2half2_rn(acc[i][0] + bb.x, acc[i][1] + bb.y);
        outp[r*64 + tx*2 + 1] = __floats2half2_rn(acc[i][2] + bb.z, acc[i][3] + bb.w);
    }
}

// ---------------- gates + c/h update: all batches per block ----------------
// grid 16 blocks (8 j-rows each), 256 threads: warp = j_local, lane = batch.
// Weights read ONCE total (warp-uniform broadcast LDGs, L1-resident rows).
__global__ __launch_bounds__(256) void gates_kernel(
        const float* __restrict__ Wih, const float* __restrict__ Whh,
        const float* __restrict__ bih, const float* __restrict__ bhh, int buf) {
    __shared__ float xs[256*B_];     // 32KB k-major copy of g_xT[buf]
    int t = threadIdx.x;
    const float4* src = (const float4*)g_xT[buf];
    float4* dst4 = (float4*)xs;
    #pragma unroll
    for (int i = 0; i < 8; i++) dst4[t + i*256] = src[t + i*256];
    __syncthreads();

    int b = t & 31, jl = t >> 5;
    int j = blockIdx.x * 8 + jl;
    const float4* Wih4 = (const float4*)Wih;
    const float4* Whh4 = (const float4*)Whh;

    float ai = 0.f, af = 0.f, ag = 0.f, ao = 0.f;
    // first half: s . Wih  (k = 0..127)
    #pragma unroll 8
    for (int kk = 0; kk < 32; kk++) {
        float4 wi = __ldg(&Wih4[(0*H_+j)*32 + kk]);
        float4 wf = __ldg(&Wih4[(1*H_+j)*32 + kk]);
        float4 wg = __ldg(&Wih4[(2*H_+j)*32 + kk]);
        float4 wo = __ldg(&Wih4[(3*H_+j)*32 + kk]);
        float x0 = xs[(4*kk+0)*B_ + b], x1 = xs[(4*kk+1)*B_ + b];
        float x2 = xs[(4*kk+2)*B_ + b], x3 = xs[(4*kk+3)*B_ + b];
        ai += wi.x*x0 + wi.y*x1 + wi.z*x2 + wi.w*x3;
        af += wf.x*x0 + wf.y*x1 + wf.z*x2 + wf.w*x3;
        ag += wg.x*x0 + wg.y*x1 + wg.z*x2 + wg.w*x3;
        ao += wo.x*x0 + wo.y*x1 + wo.z*x2 + wo.w*x3;
    }
    // second half: h . Whh  (k = 128..255)
    #pragma unroll 8
    for (int kk = 0; kk < 32; kk++) {
        float4 wi = __ldg(&Whh4[(0*H_+j)*32 + kk]);
        float4 wf = __ldg(&Whh4[(1*H_+j)*32 + kk]);
        float4 wg = __ldg(&Whh4[(2*H_+j)*32 + kk]);
        float4 wo = __ldg(&Whh4[(3*H_+j)*32 + kk]);
        float x0 = xs[(H_+4*kk+0)*B_ + b], x1 = xs[(H_+4*kk+1)*B_ + b];
        float x2 = xs[(H_+4*kk+2)*B_ + b], x3 = xs[(H_+4*kk+3)*B_ + b];
        ai += wi.x*x0 + wi.y*x1 + wi.z*x2 + wi.w*x3;
        af += wf.x*x0 + wf.y*x1 + wf.z*x2 + wf.w*x3;
        ag += wg.x*x0 + wg.y*x1 + wg.z*x2 + wg.w*x3;
        ao += wo.x*x0 + wo.y*x1 + wo.z*x2 + wo.w*x3;
    }
    ai += __ldg(&bih[j])        + __ldg(&bhh[j]);
    af += __ldg(&bih[H_+j])     + __ldg(&bhh[H_+j]);
    ag += __ldg(&bih[2*H_+j])   + __ldg(&bhh[2*H_+j]);
    ao += __ldg(&bih[3*H_+j])   + __ldg(&bhh[3*H_+j]);

    float cold = g_cT[j*B_ + b];
    float cn = sigmoid_f(af) * cold + sigmoid_f(ai) * tanhf(ag);
    float hn = sigmoid_f(ao) * tanhf(cn);
    g_cT[j*B_ + b] = cn;
    g_xT[buf ^ 1][(H_+j)*B_ + b] = hn;   // h part of next step's x
    g_xnT[j*B_ + b] = hn;                // xn = [h_new | c_new] for dec_fea
    g_xnT[(H_+j)*B_ + b] = cn;
}

// ---------------- dec_fea = xn @ W_x : all batches per block ---------------
// grid 16 blocks (8 a-cols each), 256 threads: warp = a_local, lane = batch.
__global__ __launch_bounds__(256) void dec_kernel(const float* __restrict__ Wx) {
    int b = threadIdx.x & 31, al = threadIdx.x >> 5;
    int a = blockIdx.x * 8 + al;
    float acc = 0.f;
    #pragma unroll 8
    for (int k = 0; k < 256; k++)
        acc = fmaf(g_xnT[k*B_ + b], __ldg(&Wx[k*A_ + a]), acc);
    g_dec[b*A_ + a] = acc;
}

// ---------------- attention scores + partial context (the hot kernel) ------
// grid (CH_, B_), block 256 (8 warps); warp processes TILE_/8 = 32 rows
__global__ __launch_bounds__(256) void score_kernel(
        const float* __restrict__ z, const float* __restrict__ mask,
        const float* __restrict__ wc, const float* __restrict__ v) {
    int b = blockIdx.y, chunk = blockIdx.x;
    int warp = threadIdx.x >> 5, lane = threadIdx.x & 31;

    float4 dec4 = *(const float4*)&g_dec[b*A_ + lane*4];
    float4 wc4  = __ldg(&((const float4*)wc)[lane]);
    float4 v4   = __ldg(&((const float4*)v)[lane]);

    float4 ct = make_float4(0.f, 0.f, 0.f, 0.f);
    float Sacc = 0.0f;

    int n0 = chunk * TILE_ + warp * (TILE_/8);
    const __half2* zfh = (const __half2*)g_zfh;
    const float4*  z4p = (const float4*)z;

    #pragma unroll 2
    for (int r = 0; r < TILE_/8; r++) {
        int idx = b*N_ + n0 + r;
        float cov = g_cov[idx];
        float m   = __ldg(&mask[idx]);
        float2 fa = __half22float2(zfh[(size_t)idx*64 + lane*2]);
        float2 fb = __half22float2(zfh[(size_t)idx*64 + lane*2 + 1]);
        float t0 = tanh_fast(fmaf(cov, wc4.x, fa.x) + dec4.x);
        float t1 = tanh_fast(fmaf(cov, wc4.y, fa.y) + dec4.y);
        float t2 = tanh_fast(fmaf(cov, wc4.z, fb.x) + dec4.z);
        float t3 = tanh_fast(fmaf(cov, wc4.w, fb.y) + dec4.w);
        float e = v4.x*t0 + v4.y*t1 + v4.z*t2 + v4.w*t3;
        #pragma unroll
        for (int o = 16; o > 0; o >>= 1) e += __shfl_xor_sync(0xffffffffu, e, o);
        // e bounded by ||v||_1 (~9): exp(e) cannot overflow, skip global max
        float p = (m > 0.0f) ? __expf(e) : 0.0f;
        float4 zr = __ldg(&z4p[(size_t)idx*32 + lane]);
        ct.x = fmaf(p, zr.x, ct.x);
        ct.y = fmaf(p, zr.y, ct.y);
        ct.z = fmaf(p, zr.z, ct.z);
        ct.w = fmaf(p, zr.w, ct.w);
        if (lane == 0) { g_P[idx] = p; Sacc += p; }
    }

    __shared__ float sct[DK_];
    __shared__ float sS[8];
    if (threadIdx.x < DK_) sct[threadIdx.x] = 0.0f;
    if (lane == 0) sS[warp] = Sacc;
    __syncthreads();
    atomicAdd(&sct[lane*4 + 0], ct.x);
    atomicAdd(&sct[lane*4 + 1], ct.y);
    atomicAdd(&sct[lane*4 + 2], ct.z);
    atomicAdd(&sct[lane*4 + 3], ct.w);
    __syncthreads();
    if (threadIdx.x < DK_)
        g_CTp[(b*CH_ + chunk)*DK_ + threadIdx.x] = sct[threadIdx.x];
    if (threadIdx.x == 0) {
        float S = 0.0f;
        #pragma unroll
        for (int w = 0; w < 8; w++) S += sS[w];
        g_Sp[b*CH_ + chunk] = S;
    }
}

// ---------------- finalize: normalize, outputs, coverage, closs, s=ct ------
// grid (N_/1024, B_), block 256; thread handles 4 consecutive n
__global__ __launch_bounds__(256) void finalize_kernel(float* __restrict__ out, int t, int T,
                                                       int nbuf) {
    int b = blockIdx.y;
    float S = 0.0f;
    #pragma unroll
    for (int ch = 0; ch < CH_; ch++) S += g_Sp[b*CH_ + ch];
    float invS = 1.0f / S;

    // chunk 0 blocks also produce ct -> text output + next LSTM input (s)
    if (blockIdx.x == 0 && threadIdx.x < DK_) {
        float ctv = 0.0f;
        #pragma unroll
        for (int ch = 0; ch < CH_; ch++) ctv += g_CTp[(b*CH_ + ch)*DK_ + threadIdx.x];
        ctv *= invS;
        out[(size_t)(b*T + t)*DK_ + threadIdx.x] = ctv;
        g_xT[nbuf][threadIdx.x*B_ + b] = ctv;    // s rows of next x buffer
    }

    size_t OUT_ATT = (size_t)B_ * T * DK_;
    int nbase = blockIdx.x*1024 + threadIdx.x*4;
    int idx = b*N_ + nbase;
    float4 p4 = *(const float4*)&g_P[idx];
    float4 cov4 = *(const float4*)&g_cov[idx];
    float4 attn4;
    attn4.x = p4.x * invS; attn4.y = p4.y * invS;
    attn4.z = p4.z * invS; attn4.w = p4.w * invS;
    // coverage loss uses coverage BEFORE update
    float cl = fminf(attn4.x, cov4.x) + fminf(attn4.y, cov4.y)
             + fminf(attn4.z, cov4.z) + fminf(attn4.w, cov4.w);
    float4 ncov;
    ncov.x = cov4.x + attn4.x; ncov.y = cov4.y + attn4.y;
    ncov.z = cov4.z + attn4.z; ncov.w = cov4.w + attn4.w;
    *(float4*)&g_cov[idx] = ncov;
    *(float4*)&out[OUT_ATT + (size_t)(b*T + t)*N_ + nbase] = attn4;

    #pragma unroll
    for (int o = 16; o > 0; o >>= 1) cl += __shfl_xor_sync(0xffffffffu, cl, o);
    __shared__ float swr[8];
    int warp = threadIdx.x >> 5, lane = threadIdx.x & 31;
    if (lane == 0) swr[warp] = cl;
    __syncthreads();
    if (threadIdx.x == 0) {
        float s = 0.0f;
        #pragma unroll
        for (int w = 0; w < 8; w++) s += swr[w];
        atomicAdd(&g_closs, s / (float)B_);
    }
}

__global__ void closs_write_kernel(float* __restrict__ out, int out_size) {
    out[out_size - 1] = g_closs;
}

// ---------------- host driver ----------------------------------------------
extern "C" void kernel_launch(void* const* d_in, const int* in_sizes, int n_in,
                              void* d_out, int out_size) {
    const float* z     = (const float*)d_in[0];
    const float* mask  = (const float*)d_in[1];
    const float* h0    = (const float*)d_in[2];
    const float* c0    = (const float*)d_in[3];
    const float* W_ih  = (const float*)d_in[4];
    const float* W_hh  = (const float*)d_in[5];
    const float* b_ih  = (const float*)d_in[6];
    const float* b_hh  = (const float*)d_in[7];
    const float* W_x   = (const float*)d_in[8];
    const float* W_z   = (const float*)d_in[9];
    const float* w_c   = (const float*)d_in[10];
    const float* b_attn= (const float*)d_in[11];
    const float* v     = (const float*)d_in[12];
    float* out = (float*)d_out;

    // derive step count from output buffer size: out = B*T*DK + B*T*N + 1
    int T = (out_size - 1) / (B_ * (DK_ + N_));

    init_kernel<<<(B_*N_ + 255)/256, 256>>>(h0, c0);
    zfea_kernel<<<(B_*N_)/64, 256>>>(z, W_z, b_attn);

    for (int t = 0; t < T; t++) {
        int buf = t & 1;
        gates_kernel<<<16, 256>>>(W_ih, W_hh, b_ih, b_hh, buf);
        dec_kernel<<<16, 256>>>(W_x);
        score_kernel<<<dim3(CH_, B_), 256>>>(z, mask, w_c, v);
        finalize_kernel<<<dim3(N_/1024, B_), 256>>>(out, t, T, buf ^ 1);
    }
    closs_write_kernel<<<1, 1>>>(out, out_size);
}

// round 4
// speedup vs baseline: 2.2706x; 1.5934x over previous
#include <cuda_runtime.h>
#include <cuda_fp16.h>
#include <cuda_bf16.h>

// Problem constants
#define B_   32
#define N_   4096
#define DK_  128
#define H_   128
#define A_   128
#define CH_  16
#define TILE_ 256
#define GRID_ 512

// ---------------- scratch (device globals) ---------------------------------
__device__ __half g_zfh[B_*N_*A_];     // fp16 z@W_z + b_attn (33.5MB)
__device__ float g_P[B_*N_];           // unnormalized exp scores
__device__ float g_cov[B_*N_];         // coverage
__device__ float g_s[B_*DK_];          // prev context (LSTM input)
__device__ float g_hbuf[2][B_*H_];     // double-buffered hidden state
__device__ float g_c[B_*H_];           // cell state
__device__ float g_xn[B_*2*H_];        // [h_new | c_new] per batch
__device__ float g_dec[B_*A_];         // dec_fea
__device__ float g_WxT[A_*2*H_];       // transposed W_x: [a][k]
__device__ float g_Sp[B_*CH_];         // partial softmax denominators
__device__ float g_CTp[B_*CH_*DK_];    // partial context vectors
__device__ float g_clp[GRID_];         // per-block closs partials (deterministic)
__device__ unsigned g_bcnt;            // grid barrier counter
__device__ unsigned g_bgen;            // grid barrier generation

__device__ __forceinline__ float tanh_fast(float x) {
    float y; asm("tanh.approx.f32 %0, %1;" : "=f"(y) : "f"(x)); return y;
}
__device__ __forceinline__ float sigmoid_f(float x) {
    return 1.0f / (1.0f + __expf(-x));
}

// Software grid barrier. Safe: all GRID_ blocks are co-resident
// (launch_bounds(256,4) -> >=4 blocks/SM, 148*4=592 >= 512).
__device__ __forceinline__ void grid_sync() {
    __syncthreads();
    if (threadIdx.x == 0) {
        __threadfence();
        unsigned gen = *(volatile unsigned*)&g_bgen;
        if (atomicAdd(&g_bcnt, 1u) == GRID_ - 1u) {
            g_bcnt = 0;
            __threadfence();
            *(volatile unsigned*)&g_bgen = gen + 1u;
        } else {
            while (*(volatile unsigned*)&g_bgen == gen) __nanosleep(64);
        }
        __threadfence();
    }
    __syncthreads();
}

// ---------------- z_fea = z @ W_z + b_attn  (one-time GEMM, fp16 out) ------
__global__ void zfea_kernel(const float* __restrict__ z, const float* __restrict__ Wz,
                            const float* __restrict__ battn) {
    __shared__ float zs[64*DK_];
    int t = threadIdx.x;
    int rowBase = blockIdx.x * 64;
    const float* zsrc = z + (size_t)rowBase * DK_;
    #pragma unroll
    for (int k = 0; k < 32; k++) zs[t + k*256] = zsrc[t + k*256];
    __syncthreads();

    int tx = t & 31, ty = t >> 5;
    float acc[8][4];
    #pragma unroll
    for (int i = 0; i < 8; i++)
        #pragma unroll
        for (int c = 0; c < 4; c++) acc[i][c] = 0.0f;

    const float4* Wz4 = (const float4*)Wz;
    #pragma unroll 4
    for (int d = 0; d < DK_; d++) {
        float4 w = __ldg(&Wz4[d*32 + tx]);
        #pragma unroll
        for (int i = 0; i < 8; i++) {
            float zv = zs[(ty + 8*i)*DK_ + d];
            acc[i][0] = fmaf(zv, w.x, acc[i][0]);
            acc[i][1] = fmaf(zv, w.y, acc[i][1]);
            acc[i][2] = fmaf(zv, w.z, acc[i][2]);
            acc[i][3] = fmaf(zv, w.w, acc[i][3]);
        }
    }
    float4 bb = __ldg(&((const float4*)battn)[tx]);
    __half2* outp = (__half2*)g_zfh;
    #pragma unroll
    for (int i = 0; i < 8; i++) {
        size_t r = rowBase + ty + 8*i;
        outp[r*64 + tx*2]     = __floats2half2_rn(acc[i][0] + bb.x, acc[i][1] + bb.y);
        outp[r*64 + tx*2 + 1] = __floats2half2_rn(acc[i][2] + bb.z, acc[i][3] + bb.w);
    }
}

// ---------------- persistent step loop: gates -> dec -> score -> finalize --
__global__ __launch_bounds__(256, 4) void persistent_kernel(
        float* __restrict__ out, int T, int out_size,
        const float* __restrict__ Wih, const float* __restrict__ Whh,
        const float* __restrict__ bih, const float* __restrict__ bhh,
        const float* __restrict__ Wx,
        const float* __restrict__ z, const float* __restrict__ mask,
        const float* __restrict__ wc, const float* __restrict__ v,
        const float* __restrict__ h0, const float* __restrict__ c0) {
    int bid = blockIdx.x;
    int tid = threadIdx.x;
    int warp = tid >> 5, lane = tid & 31;
    __shared__ float shm[136];

    // ---- one-time init ----
    {
        int i = bid*256 + tid;            // 0..131071
        g_cov[i] = 0.0f;
        if (bid < 128) {                  // W_x transpose: 32768 elems
            int k = i >> 7, a = i & 127;
            g_WxT[a*(2*H_) + k] = Wx[k*A_ + a];
        }
        if (bid >= 128 && bid < 144) {    // state init: 4096 elems
            int idx = (bid-128)*256 + tid;
            g_s[idx] = 0.0f;
            g_hbuf[0][idx] = h0[idx];
            g_c[idx] = c0[idx];
        }
    }
    float closs_acc = 0.0f;               // per-block partial (thread 0 holds the sum)
    grid_sync();

    size_t OUT_ATT = (size_t)B_ * T * DK_;
    int sb = bid >> 4;                    // score/finalize: batch
    int schunk = bid & 15;                // score/finalize: chunk

    for (int t = 0; t < T; t++) {
        int hb = t & 1;

        // ======== Phase A: LSTM gates + c/h update (blocks 0..127) ========
        if (bid < 128) {
            int j = bid;                  // hidden unit
            int half = lane >> 4;         // 0: s/Wih  1: h/Whh
            int koff2 = (lane & 15) * 2;  // float4 index within row
            const float4* Wih4 = (const float4*)Wih;
            const float4* Whh4 = (const float4*)Whh;
            #pragma unroll 4
            for (int i = 0; i < 16; i++) {
                int o = warp*16 + i;      // output id: gate*32 + b
                int gate = o >> 5, bb = o & 31;
                int r = gate*H_ + j;      // weight row
                const float4* Wp4 = half ? Whh4 : Wih4;
                const float4* xp4 = half ? (const float4*)&g_hbuf[hb][bb*H_]
                                         : (const float4*)&g_s[bb*DK_];
                float4 w0 = __ldg(&Wp4[r*32 + koff2]);
                float4 w1 = __ldg(&Wp4[r*32 + koff2 + 1]);
                float4 x0 = xp4[koff2];
                float4 x1 = xp4[koff2 + 1];
                float acc = w0.x*x0.x + w0.y*x0.y + w0.z*x0.z + w0.w*x0.w
                          + w1.x*x1.x + w1.y*x1.y + w1.z*x1.z + w1.w*x1.w;
                #pragma unroll
                for (int off = 16; off > 0; off >>= 1)
                    acc += __shfl_xor_sync(0xffffffffu, acc, off);
                if (lane == 0) shm[o] = acc + __ldg(&bih[r]) + __ldg(&bhh[r]);
            }
            __syncthreads();
            if (tid < 32) {
                int bb = tid;
                float ig = sigmoid_f(shm[bb]);
                float fg = sigmoid_f(shm[32 + bb]);
                float gg = tanhf(shm[64 + bb]);
                float og = sigmoid_f(shm[96 + bb]);
                float cold = g_c[bb*H_ + j];
                float cn = fg * cold + ig * gg;
                float hn = og * tanhf(cn);
                g_c[bb*H_ + j] = cn;
                g_hbuf[hb ^ 1][bb*H_ + j] = hn;
                g_xn[bb*2*H_ + j] = hn;
                g_xn[bb*2*H_ + H_ + j] = cn;
            }
        }
        grid_sync();

        // ======== Phase B: dec_fea = xn @ W_x (blocks 0..127) ========
        if (bid < 128) {
            int a = bid;
            const float4* WxT4 = (const float4*)g_WxT;
            float4 w0 = WxT4[a*64 + lane*2];
            float4 w1 = WxT4[a*64 + lane*2 + 1];
            #pragma unroll
            for (int i = 0; i < 4; i++) {
                int bb = warp*4 + i;
                const float4* xn4 = (const float4*)&g_xn[bb*2*H_];
                float4 x0 = xn4[lane*2];
                float4 x1 = xn4[lane*2 + 1];
                float acc = w0.x*x0.x + w0.y*x0.y + w0.z*x0.z + w0.w*x0.w
                          + w1.x*x1.x + w1.y*x1.y + w1.z*x1.z + w1.w*x1.w;
                #pragma unroll
                for (int off = 16; off > 0; off >>= 1)
                    acc += __shfl_xor_sync(0xffffffffu, acc, off);
                if (lane == 0) g_dec[bb*A_ + a] = acc;
            }
        }
        grid_sync();

        // ======== Phase C: attention scores + partial context (all) ========
        {
            int b = sb, chunk = schunk;
            float4 dec4 = *(const float4*)&g_dec[b*A_ + lane*4];
            float4 wc4  = __ldg(&((const float4*)wc)[lane]);
            float4 v4   = __ldg(&((const float4*)v)[lane]);

            float4 ct = make_float4(0.f, 0.f, 0.f, 0.f);
            float Sacc = 0.0f;
            int n0 = chunk * TILE_ + warp * 32;
            const __half2* zfh = (const __half2*)g_zfh;
            const float4*  z4p = (const float4*)z;

            #pragma unroll 2
            for (int r = 0; r < 32; r++) {
                int idx = b*N_ + n0 + r;
                float cov = g_cov[idx];
                float m   = __ldg(&mask[idx]);
                float2 fa = __half22float2(zfh[(size_t)idx*64 + lane*2]);
                float2 fb = __half22float2(zfh[(size_t)idx*64 + lane*2 + 1]);
                float t0 = tanh_fast(fmaf(cov, wc4.x, fa.x) + dec4.x);
                float t1 = tanh_fast(fmaf(cov, wc4.y, fa.y) + dec4.y);
                float t2 = tanh_fast(fmaf(cov, wc4.z, fb.x) + dec4.z);
                float t3 = tanh_fast(fmaf(cov, wc4.w, fb.y) + dec4.w);
                float e = v4.x*t0 + v4.y*t1 + v4.z*t2 + v4.w*t3;
                #pragma unroll
                for (int off = 16; off > 0; off >>= 1)
                    e += __shfl_xor_sync(0xffffffffu, e, off);
                // e bounded by ||v||_1 (~9): exp cannot overflow, skip global max
                float p = (m > 0.0f) ? __expf(e) : 0.0f;
                float4 zr = __ldg(&z4p[(size_t)idx*32 + lane]);
                ct.x = fmaf(p, zr.x, ct.x);
                ct.y = fmaf(p, zr.y, ct.y);
                ct.z = fmaf(p, zr.z, ct.z);
                ct.w = fmaf(p, zr.w, ct.w);
                if (lane == 0) { g_P[idx] = p; Sacc += p; }
            }

            if (tid < DK_) shm[tid] = 0.0f;
            if (lane == 0) shm[128 + warp] = Sacc;
            __syncthreads();
            atomicAdd(&shm[lane*4 + 0], ct.x);
            atomicAdd(&shm[lane*4 + 1], ct.y);
            atomicAdd(&shm[lane*4 + 2], ct.z);
            atomicAdd(&shm[lane*4 + 3], ct.w);
            __syncthreads();
            if (tid < DK_)
                g_CTp[(b*CH_ + chunk)*DK_ + tid] = shm[tid];
            if (tid == 0) {
                float S = 0.0f;
                #pragma unroll
                for (int w = 0; w < 8; w++) S += shm[128 + w];
                g_Sp[b*CH_ + chunk] = S;
            }
            __syncthreads();
        }
        grid_sync();

        // ======== Phase D: finalize (all blocks) ========
        {
            int b = sb, seg = schunk;
            if (tid < CH_) shm[tid] = g_Sp[b*CH_ + tid];
            __syncthreads();
            float S = 0.0f;
            #pragma unroll
            for (int ch = 0; ch < CH_; ch++) S += shm[ch];
            float invS = 1.0f / S;

            if (seg == 0 && tid < DK_) {
                float ctv = 0.0f;
                #pragma unroll
                for (int ch = 0; ch < CH_; ch++)
                    ctv += g_CTp[(b*CH_ + ch)*DK_ + tid];
                ctv *= invS;
                out[(size_t)(b*T + t)*DK_ + tid] = ctv;
                g_s[b*DK_ + tid] = ctv;         // next LSTM input
            }

            int n = seg*256 + tid;
            int idx = b*N_ + n;
            float p = g_P[idx];
            float cov = g_cov[idx];
            float attn = p * invS;
            float cl = fminf(attn, cov);        // coverage BEFORE update
            g_cov[idx] = cov + attn;
            out[OUT_ATT + (size_t)(b*T + t)*N_ + n] = attn;

            #pragma unroll
            for (int off = 16; off > 0; off >>= 1)
                cl += __shfl_xor_sync(0xffffffffu, cl, off);
            __syncthreads();                    // shm reuse guard
            if (lane == 0) shm[16 + warp] = cl;
            __syncthreads();
            if (tid == 0) {
                float s = 0.0f;
                #pragma unroll
                for (int w = 0; w < 8; w++) s += shm[16 + w];
                closs_acc += s;
            }
        }
        grid_sync();
    }

    // deterministic closs: ordered reduction of per-block partials
    if (tid == 0) g_clp[bid] = closs_acc;
    grid_sync();
    if (bid == 0 && tid == 0) {
        float s = 0.0f;
        for (int i = 0; i < GRID_; i++) s += g_clp[i];
        out[out_size - 1] = s / (float)B_;
    }
}

// ---------------- host driver ----------------------------------------------
extern "C" void kernel_launch(void* const* d_in, const int* in_sizes, int n_in,
                              void* d_out, int out_size) {
    const float* z     = (const float*)d_in[0];
    const float* mask  = (const float*)d_in[1];
    const float* h0    = (const float*)d_in[2];
    const float* c0    = (const float*)d_in[3];
    const float* W_ih  = (const float*)d_in[4];
    const float* W_hh  = (const float*)d_in[5];
    const float* b_ih  = (const float*)d_in[6];
    const float* b_hh  = (const float*)d_in[7];
    const float* W_x   = (const float*)d_in[8];
    const float* W_z   = (const float*)d_in[9];
    const float* w_c   = (const float*)d_in[10];
    const float* b_attn= (const float*)d_in[11];
    const float* v     = (const float*)d_in[12];
    float* out = (float*)d_out;

    int T = (out_size - 1) / (B_ * (DK_ + N_));

    zfea_kernel<<<(B_*N_)/64, 256>>>(z, W_z, b_attn);
    persistent_kernel<<<GRID_, 256>>>(out, T, out_size,
                                      W_ih, W_hh, b_ih, b_hh, W_x,
                                      z, mask, w_c, v, h0, c0);
}